// round 2
// baseline (speedup 1.0000x reference)
#include <cuda_runtime.h>
#include <math.h>

#define N_NODES_MAX 100000
#define N_EDGES_MAX 1600000

// -------- scratch (static __device__; no allocation at launch time) --------
__device__ float  g_emb0[N_EDGES_MAX];
__device__ float  g_emb1[N_EDGES_MAX];
__device__ float  g_emb2[N_EDGES_MAX];
__device__ float4 g_xA[N_NODES_MAX];
__device__ float4 g_xB[N_NODES_MAX];
__device__ float  g_M[128];   // fused fc3_w2 x conv_w : [k=16][u=4][c=2]

// -------- constants (all e3nn normalization folded) --------
// emb scale: C_smooth * sqrt(num_basis) = 1.14136*e^2*sqrt(3)
#define EMBC  (1.14136f * 7.38905609893065f * 1.7320508075688772f)
// h = sqrt(2)*relu(emb @ W1/sqrt(3)); w = h @ W2/sqrt(16); msg *= path_w; sum /= sqrt(z)=4
// conv1: path_w = 1/sqrt(3)  ->  C1 = sqrt(2)/48
#define C1    (1.41421356237f / 48.0f)
// core & conv3: path_w = 0.5  ->  C = sqrt(2)/(sqrt(3)*32)
#define CCORE (1.41421356237f / (1.7320508075688772f * 32.0f))

// -------- vectorized global reductions (sm_90+) --------
__device__ __forceinline__ void red_add_v4(float4* addr, float a, float b, float c, float d) {
    asm volatile("red.global.add.v4.f32 [%0], {%1, %2, %3, %4};"
                 :: "l"(addr), "f"(a), "f"(b), "f"(c), "f"(d) : "memory");
}
__device__ __forceinline__ void red_add_v2(float* addr, float a, float b) {
    asm volatile("red.global.add.v2.f32 [%0], {%1, %2};"
                 :: "l"(addr), "f"(a), "f"(b) : "memory");
}

// ============================================================================
__global__ void __launch_bounds__(256) zero_nodes_kernel(float4* __restrict__ p, int n) {
    int i = blockIdx.x * 256 + threadIdx.x;
    if (i < n) p[i] = make_float4(0.f, 0.f, 0.f, 0.f);
}

__global__ void init_out_kernel(float* __restrict__ out, const float* __restrict__ conv_b, int n) {
    int i = blockIdx.x * 256 + threadIdx.x;
    if (i < n) {
        float2 b = make_float2(conv_b[0], conv_b[1]);
        ((float2*)out)[i] = b;
    }
}

// Precompute M[k,u,c] = CCORE * sum_w fc3_w2[k, u*16+w] * conv_w[c, w]
__global__ void mprep_kernel(const float* __restrict__ fc3_w2, const float* __restrict__ conv_w) {
    int t = threadIdx.x;            // 128 threads
    int k = t >> 3;
    int u = (t >> 1) & 3;
    int c = t & 1;
    float s = 0.f;
#pragma unroll
    for (int w = 0; w < 16; w++)
        s += fc3_w2[k * 64 + u * 16 + w] * conv_w[c * 16 + w];
    g_M[t] = CCORE * s;             // layout: k*8 + u*2 + c
}

// ============================================================================
// conv1 (fused with edge-length / embedding precompute):
//   emb -> r[16]=relu(emb@W1) -> acc[3*4]=r@W2[:, :12] -> msg = C1 * feat[src]·acc
__global__ void __launch_bounds__(256) conv1_kernel(
    const float* __restrict__ pos, const float* __restrict__ feat,
    const int* __restrict__ esrc, const int* __restrict__ edst,
    const float* __restrict__ w1, const float* __restrict__ w2,
    float4* __restrict__ xout, int E)
{
    __shared__ float sW1[48];
    __shared__ float sW2[192];
    int t = threadIdx.x;
    if (t < 48)  sW1[t] = w1[t];
    if (t < 192) sW2[t] = w2[t];
    __syncthreads();

    int e = blockIdx.x * 256 + t;
    if (e >= E) return;
    int s = esrc[e], d = edst[e];

    float dx = pos[3 * d + 0] - pos[3 * s + 0];
    float dy = pos[3 * d + 1] - pos[3 * s + 1];
    float dz = pos[3 * d + 2] - pos[3 * s + 2];
    float dist = sqrtf(dx * dx + dy * dy + dz * dz);

    float f0 = feat[3 * s + 0];
    float f1 = feat[3 * s + 1];
    float f2 = feat[3 * s + 2];

    float em[3];
#pragma unroll
    for (int i = 0; i < 3; i++) {
        float tt = (dist - 0.75f * (float)(i + 1)) * (1.0f / 0.75f);
        float q = 1.0f - tt * tt;
        // sus(t+1)*sus(1-t) = exp(-2/(1-t^2)) for |t|<1 else 0
        em[i] = (q > 0.0f) ? EMBC * __expf(__fdividef(-2.0f, q)) : 0.0f;
    }
    g_emb0[e] = em[0]; g_emb1[e] = em[1]; g_emb2[e] = em[2];

    float r[16];
#pragma unroll
    for (int k = 0; k < 16; k++)
        r[k] = fmaxf(em[0] * sW1[k] + em[1] * sW1[16 + k] + em[2] * sW1[32 + k], 0.f);

    float acc[12];
#pragma unroll
    for (int j = 0; j < 12; j++) acc[j] = 0.f;
#pragma unroll
    for (int k = 0; k < 16; k++) {
#pragma unroll
        for (int j = 0; j < 12; j++) acc[j] += r[k] * sW2[k * 12 + j];
    }

    float m0 = C1 * (f0 * acc[0] + f1 * acc[4] + f2 * acc[8]);
    float m1 = C1 * (f0 * acc[1] + f1 * acc[5] + f2 * acc[9]);
    float m2 = C1 * (f0 * acc[2] + f1 * acc[6] + f2 * acc[10]);
    float m3 = C1 * (f0 * acc[3] + f1 * acc[7] + f2 * acc[11]);
    red_add_v4(&xout[d], m0, m1, m2, m3);
}

// ============================================================================
// core conv (x4 -> x4): r[16]=relu(emb@W1); acc[16]=r@W2[:, :16]; msg = C*x·acc
__global__ void __launch_bounds__(256) core_kernel(
    const int* __restrict__ esrc, const int* __restrict__ edst,
    const float* __restrict__ w1, const float* __restrict__ w2, // w2: [16,48] raw
    const float4* __restrict__ xin, float4* __restrict__ xout, int E)
{
    __shared__ float sW1[48];
    __shared__ float sW2[256];
    int t = threadIdx.x;
    if (t < 48) sW1[t] = w1[t];
    {   // sW2[k*16+j] = w2[k*48+j], j<16
        int k = t >> 4, j = t & 15;
        sW2[t] = w2[k * 48 + j];
    }
    __syncthreads();

    int e = blockIdx.x * 256 + t;
    if (e >= E) return;
    int s = esrc[e], d = edst[e];

    float4 x = xin[s];
    float e0 = g_emb0[e], e1 = g_emb1[e], e2 = g_emb2[e];

    float r[16];
#pragma unroll
    for (int k = 0; k < 16; k++)
        r[k] = fmaxf(e0 * sW1[k] + e1 * sW1[16 + k] + e2 * sW1[32 + k], 0.f);

    float acc[16];
#pragma unroll
    for (int j = 0; j < 16; j++) acc[j] = 0.f;
#pragma unroll
    for (int k = 0; k < 16; k++) {
#pragma unroll
        for (int j = 0; j < 16; j++) acc[j] += r[k] * sW2[k * 16 + j];
    }

    // acc index = u*4 + w
    float m0 = CCORE * (x.x * acc[0] + x.y * acc[4] + x.z * acc[8]  + x.w * acc[12]);
    float m1 = CCORE * (x.x * acc[1] + x.y * acc[5] + x.z * acc[9]  + x.w * acc[13]);
    float m2 = CCORE * (x.x * acc[2] + x.y * acc[6] + x.z * acc[10] + x.w * acc[14]);
    float m3 = CCORE * (x.x * acc[3] + x.y * acc[7] + x.z * acc[11] + x.w * acc[15]);
    red_add_v4(&xout[d], m0, m1, m2, m3);
}

// ============================================================================
// conv3 fused with final Conv1d(16,2,1): msg[c] = sum_u x[u] * sum_k r[k]*M[k,u,c]
// (scale + conv weights folded into M; bias pre-initialized into out)
__global__ void __launch_bounds__(256) conv3_kernel(
    const int* __restrict__ esrc, const int* __restrict__ edst,
    const float* __restrict__ w1,            // fc3_w1 [3,16]
    const float4* __restrict__ xin, float* __restrict__ out, int E)
{
    __shared__ float sW1[48];
    __shared__ float sM[128];
    int t = threadIdx.x;
    if (t < 48)  sW1[t] = w1[t];
    if (t < 128) sM[t] = g_M[t];
    __syncthreads();

    int e = blockIdx.x * 256 + t;
    if (e >= E) return;
    int s = esrc[e], d = edst[e];

    float4 x = xin[s];
    float e0 = g_emb0[e], e1 = g_emb1[e], e2 = g_emb2[e];

    float r[16];
#pragma unroll
    for (int k = 0; k < 16; k++)
        r[k] = fmaxf(e0 * sW1[k] + e1 * sW1[16 + k] + e2 * sW1[32 + k], 0.f);

    float acc[8];
#pragma unroll
    for (int j = 0; j < 8; j++) acc[j] = 0.f;
#pragma unroll
    for (int k = 0; k < 16; k++) {
#pragma unroll
        for (int j = 0; j < 8; j++) acc[j] += r[k] * sM[k * 8 + j];
    }

    // acc index = u*2 + c
    float m0 = x.x * acc[0] + x.y * acc[2] + x.z * acc[4] + x.w * acc[6];
    float m1 = x.x * acc[1] + x.y * acc[3] + x.z * acc[5] + x.w * acc[7];
    red_add_v2(out + 2 * d, m0, m1);
}

// ============================================================================
extern "C" void kernel_launch(void* const* d_in, const int* in_sizes, int n_in,
                              void* d_out, int out_size)
{
    const float* pos     = (const float*)d_in[0];
    const float* feat    = (const float*)d_in[1];
    const int*   esrc    = (const int*)  d_in[2];
    const int*   edst    = (const int*)  d_in[3];
    const float* fc1_w1  = (const float*)d_in[4];
    const float* fc1_w2  = (const float*)d_in[5];
    const float* core_w1 = (const float*)d_in[6];   // [3,3,16]
    const float* core_w2 = (const float*)d_in[7];   // [3,16,48]
    const float* fc3_w1  = (const float*)d_in[8];
    const float* fc3_w2  = (const float*)d_in[9];
    const float* conv_w  = (const float*)d_in[10];
    const float* conv_b  = (const float*)d_in[11];
    float* out = (float*)d_out;

    int E = in_sizes[2];
    int n = in_sizes[0] / 3;

    float4 *xA, *xB;
    cudaGetSymbolAddress((void**)&xA, g_xA);
    cudaGetSymbolAddress((void**)&xB, g_xB);

    int eb = (E + 255) / 256;
    int nb = (n + 255) / 256;

    mprep_kernel<<<1, 128>>>(fc3_w2, conv_w);
    zero_nodes_kernel<<<nb, 256>>>(xA, n);
    conv1_kernel<<<eb, 256>>>(pos, feat, esrc, edst, fc1_w1, fc1_w2, xA, E);

    zero_nodes_kernel<<<nb, 256>>>(xB, n);
    core_kernel<<<eb, 256>>>(esrc, edst, core_w1 + 0,  core_w2 + 0,    xA, xB, E);

    zero_nodes_kernel<<<nb, 256>>>(xA, n);
    core_kernel<<<eb, 256>>>(esrc, edst, core_w1 + 48, core_w2 + 768,  xB, xA, E);

    zero_nodes_kernel<<<nb, 256>>>(xB, n);
    core_kernel<<<eb, 256>>>(esrc, edst, core_w1 + 96, core_w2 + 1536, xA, xB, E);

    init_out_kernel<<<nb, 256>>>(out, conv_b, n);
    conv3_kernel<<<eb, 256>>>(esrc, edst, fc3_w1, xB, out, E);
}

// round 3
// speedup vs baseline: 1.0205x; 1.0205x over previous
#include <cuda_runtime.h>
#include <math.h>

#define N_NODES_MAX 100000
#define N_EDGES_MAX 1600000

// -------- scratch (static __device__; no allocation at launch time) --------
__device__ float  g_emb0[N_EDGES_MAX];
__device__ float  g_emb1[N_EDGES_MAX];
__device__ float  g_emb2[N_EDGES_MAX];
__device__ float4 g_xA[N_NODES_MAX];
__device__ float4 g_xB[N_NODES_MAX];
__device__ float4 g_xC[N_NODES_MAX];
__device__ float  g_M[128];   // fused fc3_w2 x conv_w : [k=16][u=4][c=2], CCORE folded

// -------- constants (all e3nn normalization folded) --------
#define EMBC  (1.14136f * 7.38905609893065f * 1.7320508075688772f)
#define C1    (1.41421356237f / 48.0f)
#define CCORE (1.41421356237f / (1.7320508075688772f * 32.0f))

typedef unsigned long long u64;

// -------- packed f32x2 helpers (sm_100+; ptxas never auto-fuses these) -----
__device__ __forceinline__ u64 pack2(float x, float y) {
    u64 r; asm("mov.b64 %0, {%1, %2};" : "=l"(r) : "f"(x), "f"(y)); return r;
}
__device__ __forceinline__ void unpack2(u64 v, float& x, float& y) {
    asm("mov.b64 {%0, %1}, %2;" : "=f"(x), "=f"(y) : "l"(v));
}
__device__ __forceinline__ void fma2(u64& d, u64 a, u64 b) {
    asm("fma.rn.f32x2 %0, %1, %2, %0;" : "+l"(d) : "l"(a), "l"(b));
}
__device__ __forceinline__ u64 mul2(u64 a, u64 b) {
    u64 d; asm("mul.rn.f32x2 %0, %1, %2;" : "=l"(d) : "l"(a), "l"(b)); return d;
}

// -------- vectorized global reductions (sm_90+) --------
__device__ __forceinline__ void red_add_v4(float4* addr, float a, float b, float c, float d) {
    asm volatile("red.global.add.v4.f32 [%0], {%1, %2, %3, %4};"
                 :: "l"(addr), "f"(a), "f"(b), "f"(c), "f"(d) : "memory");
}
__device__ __forceinline__ void red_add_v2(float* addr, float a, float b) {
    asm volatile("red.global.add.v2.f32 [%0], {%1, %2};"
                 :: "l"(addr), "f"(a), "f"(b) : "memory");
}

// ============================================================================
__global__ void __launch_bounds__(256) zero_ab_kernel(float4* __restrict__ a,
                                                      float4* __restrict__ b, int n) {
    int i = blockIdx.x * 256 + threadIdx.x;
    if (i < n)          a[i]     = make_float4(0.f, 0.f, 0.f, 0.f);
    else if (i < 2 * n) b[i - n] = make_float4(0.f, 0.f, 0.f, 0.f);
}

__global__ void init_out_kernel(float* __restrict__ out, const float* __restrict__ conv_b, int n) {
    int i = blockIdx.x * 256 + threadIdx.x;
    if (i < n) ((float2*)out)[i] = make_float2(conv_b[0], conv_b[1]);
}

// M[k,u,c] = CCORE * sum_w fc3_w2[k, u*16+w] * conv_w[c, w]
__global__ void mprep_kernel(const float* __restrict__ fc3_w2, const float* __restrict__ conv_w) {
    int t = threadIdx.x;            // 128
    int k = t >> 3, u = (t >> 1) & 3, c = t & 1;
    float s = 0.f;
#pragma unroll
    for (int w = 0; w < 16; w++)
        s += fc3_w2[k * 64 + u * 16 + w] * conv_w[c * 16 + w];
    g_M[t] = CCORE * s;
}

// -------- shared packed r[16] computation: 24 FFMA2 + 16 MAX(alu) ----------
// sW1u layout: [i*8 + kp] = (w1[i*16+2kp], w1[i*16+2kp+1])
__device__ __forceinline__ void compute_r_pairs(const u64* sW1u, float e0, float e1, float e2,
                                                float* rlo, float* rhi) {
    u64 e02 = pack2(e0, e0), e12 = pack2(e1, e1), e22 = pack2(e2, e2);
#pragma unroll
    for (int kp = 0; kp < 8; kp++) {
        u64 v = mul2(e02, sW1u[kp]);
        fma2(v, e12, sW1u[8 + kp]);
        fma2(v, e22, sW1u[16 + kp]);
        float a, b; unpack2(v, a, b);
        rlo[kp] = fmaxf(a, 0.f);
        rhi[kp] = fmaxf(b, 0.f);
    }
}

// ============================================================================
// conv1: emb precompute + r + 16x12 GEMM (packed) + msg, scatter v4
__global__ void __launch_bounds__(256) conv1_kernel(
    const float* __restrict__ pos, const float* __restrict__ feat,
    const int* __restrict__ esrc, const int* __restrict__ edst,
    const float* __restrict__ w1, const float* __restrict__ w2,
    float4* __restrict__ xout, int E)
{
    __shared__ u64 sW1u[24];
    __shared__ u64 sW2u[96];   // [k*6 + jp], C1 folded
    int t = threadIdx.x;
    if (t < 24) {
        int i = t / 8, kp = t % 8;
        sW1u[t] = pack2(w1[i * 16 + 2 * kp], w1[i * 16 + 2 * kp + 1]);
    }
    if (t < 96) {
        int k = t / 6, jp = t % 6;
        sW2u[t] = pack2(C1 * w2[k * 12 + 2 * jp], C1 * w2[k * 12 + 2 * jp + 1]);
    }
    __syncthreads();

    int e = blockIdx.x * 256 + t;
    if (e >= E) return;
    int s = esrc[e], d = edst[e];

    float dx = pos[3 * d + 0] - pos[3 * s + 0];
    float dy = pos[3 * d + 1] - pos[3 * s + 1];
    float dz = pos[3 * d + 2] - pos[3 * s + 2];
    float dist = sqrtf(dx * dx + dy * dy + dz * dz);

    float f0 = feat[3 * s + 0], f1 = feat[3 * s + 1], f2 = feat[3 * s + 2];

    float em[3];
#pragma unroll
    for (int i = 0; i < 3; i++) {
        float tt = (dist - 0.75f * (float)(i + 1)) * (1.0f / 0.75f);
        float q = 1.0f - tt * tt;
        em[i] = (q > 0.0f) ? EMBC * __expf(__fdividef(-2.0f, q)) : 0.0f;
    }
    g_emb0[e] = em[0]; g_emb1[e] = em[1]; g_emb2[e] = em[2];

    float rlo[8], rhi[8];
    compute_r_pairs(sW1u, em[0], em[1], em[2], rlo, rhi);

    u64 acc[6];
#pragma unroll
    for (int jp = 0; jp < 6; jp++) acc[jp] = 0ull;
#pragma unroll
    for (int kp = 0; kp < 8; kp++) {
        u64 ra = pack2(rlo[kp], rlo[kp]);
        u64 rb = pack2(rhi[kp], rhi[kp]);
#pragma unroll
        for (int jp = 0; jp < 6; jp++) fma2(acc[jp], ra, sW2u[(2 * kp) * 6 + jp]);
#pragma unroll
        for (int jp = 0; jp < 6; jp++) fma2(acc[jp], rb, sW2u[(2 * kp + 1) * 6 + jp]);
    }

    // msg pairs: m01 = sum_u f_u * acc[u*2+0], m23 = sum_u f_u * acc[u*2+1]
    u64 fu[3] = { pack2(f0, f0), pack2(f1, f1), pack2(f2, f2) };
    u64 m01 = 0ull, m23 = 0ull;
#pragma unroll
    for (int u = 0; u < 3; u++) { fma2(m01, fu[u], acc[u * 2]); fma2(m23, fu[u], acc[u * 2 + 1]); }
    float m0, m1, m2, m3;
    unpack2(m01, m0, m1); unpack2(m23, m2, m3);
    red_add_v4(&xout[d], m0, m1, m2, m3);
}

// ============================================================================
// core conv: r + 16x16 GEMM packed + msg; also zeroes zbuf (next pass's accum)
__global__ void __launch_bounds__(256) core_kernel(
    const int* __restrict__ esrc, const int* __restrict__ edst,
    const float* __restrict__ w1, const float* __restrict__ w2, // w2 raw [16,48]
    const float4* __restrict__ xin, float4* __restrict__ xout,
    float4* __restrict__ zbuf, int zn, int E)
{
    __shared__ u64 sW1u[24];
    __shared__ u64 sW2u[128];  // [k*8 + jp], CCORE folded
    int t = threadIdx.x;
    if (t < 24) {
        int i = t / 8, kp = t % 8;
        sW1u[t] = pack2(w1[i * 16 + 2 * kp], w1[i * 16 + 2 * kp + 1]);
    }
    if (t < 128) {
        int k = t >> 3, jp = t & 7;
        sW2u[t] = pack2(CCORE * w2[k * 48 + 2 * jp], CCORE * w2[k * 48 + 2 * jp + 1]);
    }
    __syncthreads();

    int gid = blockIdx.x * 256 + t;
    if (gid < zn) zbuf[gid] = make_float4(0.f, 0.f, 0.f, 0.f);

    int e = gid;
    if (e >= E) return;
    int s = esrc[e], d = edst[e];

    float4 x = xin[s];
    float e0 = g_emb0[e], e1 = g_emb1[e], e2 = g_emb2[e];

    float rlo[8], rhi[8];
    compute_r_pairs(sW1u, e0, e1, e2, rlo, rhi);

    u64 acc[8];
#pragma unroll
    for (int jp = 0; jp < 8; jp++) acc[jp] = 0ull;
#pragma unroll
    for (int kp = 0; kp < 8; kp++) {
        u64 ra = pack2(rlo[kp], rlo[kp]);
        u64 rb = pack2(rhi[kp], rhi[kp]);
#pragma unroll
        for (int jp = 0; jp < 8; jp++) fma2(acc[jp], ra, sW2u[(2 * kp) * 8 + jp]);
#pragma unroll
        for (int jp = 0; jp < 8; jp++) fma2(acc[jp], rb, sW2u[(2 * kp + 1) * 8 + jp]);
    }

    // msg pairs: jp = u*2 + wp; m01 over wp=0, m23 over wp=1
    u64 xu[4] = { pack2(x.x, x.x), pack2(x.y, x.y), pack2(x.z, x.z), pack2(x.w, x.w) };
    u64 m01 = 0ull, m23 = 0ull;
#pragma unroll
    for (int u = 0; u < 4; u++) { fma2(m01, xu[u], acc[u * 2]); fma2(m23, xu[u], acc[u * 2 + 1]); }
    float m0, m1, m2, m3;
    unpack2(m01, m0, m1); unpack2(m23, m2, m3);
    red_add_v4(&xout[d], m0, m1, m2, m3);
}

// ============================================================================
// conv3 fused with Conv1d(16,2,1): acc pairs over output channel c
__global__ void __launch_bounds__(256) conv3_kernel(
    const int* __restrict__ esrc, const int* __restrict__ edst,
    const float* __restrict__ w1,
    const float4* __restrict__ xin, float* __restrict__ out, int E)
{
    __shared__ u64 sW1u[24];
    __shared__ u64 sMu[64];    // [k*4 + u] = (M[k,u,0], M[k,u,1])
    int t = threadIdx.x;
    if (t < 24) {
        int i = t / 8, kp = t % 8;
        sW1u[t] = pack2(w1[i * 16 + 2 * kp], w1[i * 16 + 2 * kp + 1]);
    }
    if (t < 64) {
        int k = t >> 2, u = t & 3;
        sMu[t] = pack2(g_M[k * 8 + u * 2], g_M[k * 8 + u * 2 + 1]);
    }
    __syncthreads();

    int e = blockIdx.x * 256 + t;
    if (e >= E) return;
    int s = esrc[e], d = edst[e];

    float4 x = xin[s];
    float e0 = g_emb0[e], e1 = g_emb1[e], e2 = g_emb2[e];

    float rlo[8], rhi[8];
    compute_r_pairs(sW1u, e0, e1, e2, rlo, rhi);

    u64 acc[4];
#pragma unroll
    for (int u = 0; u < 4; u++) acc[u] = 0ull;
#pragma unroll
    for (int kp = 0; kp < 8; kp++) {
        u64 ra = pack2(rlo[kp], rlo[kp]);
        u64 rb = pack2(rhi[kp], rhi[kp]);
#pragma unroll
        for (int u = 0; u < 4; u++) fma2(acc[u], ra, sMu[(2 * kp) * 4 + u]);
#pragma unroll
        for (int u = 0; u < 4; u++) fma2(acc[u], rb, sMu[(2 * kp + 1) * 4 + u]);
    }

    u64 xu[4] = { pack2(x.x, x.x), pack2(x.y, x.y), pack2(x.z, x.z), pack2(x.w, x.w) };
    u64 mc = 0ull;
#pragma unroll
    for (int u = 0; u < 4; u++) fma2(mc, xu[u], acc[u]);
    float m0, m1;
    unpack2(mc, m0, m1);
    red_add_v2(out + 2 * d, m0, m1);
}

// ============================================================================
extern "C" void kernel_launch(void* const* d_in, const int* in_sizes, int n_in,
                              void* d_out, int out_size)
{
    const float* pos     = (const float*)d_in[0];
    const float* feat    = (const float*)d_in[1];
    const int*   esrc    = (const int*)  d_in[2];
    const int*   edst    = (const int*)  d_in[3];
    const float* fc1_w1  = (const float*)d_in[4];
    const float* fc1_w2  = (const float*)d_in[5];
    const float* core_w1 = (const float*)d_in[6];   // [3,3,16]
    const float* core_w2 = (const float*)d_in[7];   // [3,16,48]
    const float* fc3_w1  = (const float*)d_in[8];
    const float* fc3_w2  = (const float*)d_in[9];
    const float* conv_w  = (const float*)d_in[10];
    const float* conv_b  = (const float*)d_in[11];
    float* out = (float*)d_out;

    int E = in_sizes[2];
    int n = in_sizes[0] / 3;

    float4 *xA, *xB, *xC;
    cudaGetSymbolAddress((void**)&xA, g_xA);
    cudaGetSymbolAddress((void**)&xB, g_xB);
    cudaGetSymbolAddress((void**)&xC, g_xC);

    int eb = (E + 255) / 256;
    int nb = (n + 255) / 256;
    int nb2 = (2 * n + 255) / 256;

    mprep_kernel<<<1, 128>>>(fc3_w2, conv_w);
    init_out_kernel<<<nb, 256>>>(out, conv_b, n);
    zero_ab_kernel<<<nb2, 256>>>(xA, xB, n);

    conv1_kernel<<<eb, 256>>>(pos, feat, esrc, edst, fc1_w1, fc1_w2, xA, E);
    // core1: A->B, zero C for core2's output
    core_kernel<<<eb, 256>>>(esrc, edst, core_w1 + 0,  core_w2 + 0,    xA, xB, xC, n, E);
    // core2: B->C, zero A for core3's output
    core_kernel<<<eb, 256>>>(esrc, edst, core_w1 + 48, core_w2 + 768,  xB, xC, xA, n, E);
    // core3: C->A
    core_kernel<<<eb, 256>>>(esrc, edst, core_w1 + 96, core_w2 + 1536, xC, xA, (float4*)0, 0, E);

    conv3_kernel<<<eb, 256>>>(esrc, edst, fc3_w1, xA, out, E);
}

// round 4
// speedup vs baseline: 1.0545x; 1.0333x over previous
#include <cuda_runtime.h>
#include <math.h>

#define N_NODES_MAX 100000
#define N_EDGES_MAX 1600000

typedef unsigned long long u64;
typedef ulonglong2 u64x2;

// -------- scratch (static __device__; no allocation at launch time) --------
__device__ float4 g_emb4[N_EDGES_MAX];     // (em0, em1, em2, unused)
__device__ float4 g_pos4[N_NODES_MAX];
__device__ float4 g_feat4[N_NODES_MAX];
__device__ float4 g_xA[N_NODES_MAX];
__device__ float4 g_xB[N_NODES_MAX];
__device__ float4 g_xC[N_NODES_MAX];
__device__ float  g_M[128];   // fused fc3_w2 x conv_w : [k=16][u=4][c=2], CCORE folded

// -------- constants (all e3nn normalization folded) --------
#define EMBC  (1.14136f * 7.38905609893065f * 1.7320508075688772f)
#define C1    (1.41421356237f / 48.0f)
#define CCORE (1.41421356237f / (1.7320508075688772f * 32.0f))

// -------- packed f32x2 helpers --------
__device__ __forceinline__ u64 pack2(float x, float y) {
    u64 r; asm("mov.b64 %0, {%1, %2};" : "=l"(r) : "f"(x), "f"(y)); return r;
}
__device__ __forceinline__ void unpack2(u64 v, float& x, float& y) {
    asm("mov.b64 {%0, %1}, %2;" : "=f"(x), "=f"(y) : "l"(v));
}
__device__ __forceinline__ void fma2(u64& d, u64 a, u64 b) {
    asm("fma.rn.f32x2 %0, %1, %2, %0;" : "+l"(d) : "l"(a), "l"(b));
}
__device__ __forceinline__ u64 mul2(u64 a, u64 b) {
    u64 d; asm("mul.rn.f32x2 %0, %1, %2;" : "=l"(d) : "l"(a), "l"(b)); return d;
}

// -------- vectorized global reductions (sm_90+) --------
__device__ __forceinline__ void red_add_v4(float4* addr, float a, float b, float c, float d) {
    asm volatile("red.global.add.v4.f32 [%0], {%1, %2, %3, %4};"
                 :: "l"(addr), "f"(a), "f"(b), "f"(c), "f"(d) : "memory");
}
__device__ __forceinline__ void red_add_v2(float* addr, float a, float b) {
    asm volatile("red.global.add.v2.f32 [%0], {%1, %2};"
                 :: "l"(addr), "f"(a), "f"(b) : "memory");
}

// ============================================================================
// prep: pack pos/feat into float4 tables, zero xA/xB, write bias into out
__global__ void __launch_bounds__(256) prep_kernel(
    const float* __restrict__ pos, const float* __restrict__ feat,
    const float* __restrict__ conv_b, float* __restrict__ out, int n)
{
    int i = blockIdx.x * 256 + threadIdx.x;
    if (i >= n) return;
    g_pos4[i]  = make_float4(pos[3 * i], pos[3 * i + 1], pos[3 * i + 2], 0.f);
    g_feat4[i] = make_float4(feat[3 * i], feat[3 * i + 1], feat[3 * i + 2], 0.f);
    g_xA[i] = make_float4(0.f, 0.f, 0.f, 0.f);
    g_xB[i] = make_float4(0.f, 0.f, 0.f, 0.f);
    ((float2*)out)[i] = make_float2(conv_b[0], conv_b[1]);
}

// M[k,u,c] = CCORE * sum_w fc3_w2[k, u*16+w] * conv_w[c, w]
__global__ void mprep_kernel(const float* __restrict__ fc3_w2, const float* __restrict__ conv_w) {
    int t = threadIdx.x;            // 128
    int k = t >> 3, u = (t >> 1) & 3, c = t & 1;
    float s = 0.f;
#pragma unroll
    for (int w = 0; w < 16; w++)
        s += fc3_w2[k * 64 + u * 16 + w] * conv_w[c * 16 + w];
    g_M[t] = CCORE * s;
}

// -------- packed r[16]: 12 LDS.128 + 24 FFMA2 + 16 MAX ----------
// sW1u layout: [i*8 + kp] = (w1[i*16+2kp], w1[i*16+2kp+1]) ; i = input idx
__device__ __forceinline__ void compute_r_pairs(const u64* sW1u, float e0, float e1, float e2,
                                                float* rlo, float* rhi) {
    u64 e02 = pack2(e0, e0), e12 = pack2(e1, e1), e22 = pack2(e2, e2);
    const u64x2* w0 = (const u64x2*)(sW1u);
    const u64x2* w1 = (const u64x2*)(sW1u + 8);
    const u64x2* w2 = (const u64x2*)(sW1u + 16);
#pragma unroll
    for (int q = 0; q < 4; q++) {           // q covers kp pair (2q, 2q+1)
        u64x2 a = w0[q], b = w1[q], c = w2[q];
        u64 v0 = mul2(e02, a.x);
        u64 v1 = mul2(e02, a.y);
        fma2(v0, e12, b.x); fma2(v1, e12, b.y);
        fma2(v0, e22, c.x); fma2(v1, e22, c.y);
        float p, r; unpack2(v0, p, r);
        rlo[2 * q] = fmaxf(p, 0.f); rhi[2 * q] = fmaxf(r, 0.f);
        unpack2(v1, p, r);
        rlo[2 * q + 1] = fmaxf(p, 0.f); rhi[2 * q + 1] = fmaxf(r, 0.f);
    }
}

// ============================================================================
// conv1: emb precompute + r + 16x12 GEMM (packed, vec LDS) + msg, scatter v4
__global__ void __launch_bounds__(256) conv1_kernel(
    const int* __restrict__ esrc, const int* __restrict__ edst,
    const float* __restrict__ w1, const float* __restrict__ w2,
    float4* __restrict__ xout, int E)
{
    __shared__ __align__(16) u64 sW1u[24];
    __shared__ __align__(16) u64 sW2u[96];   // [k*6 + jp], C1 folded; rows 48B (16B aligned)
    int t = threadIdx.x;
    if (t < 24) {
        int i = t / 8, kp = t % 8;
        sW1u[t] = pack2(w1[i * 16 + 2 * kp], w1[i * 16 + 2 * kp + 1]);
    }
    if (t < 96) {
        int k = t / 6, jp = t % 6;
        sW2u[t] = pack2(C1 * w2[k * 12 + 2 * jp], C1 * w2[k * 12 + 2 * jp + 1]);
    }
    __syncthreads();

    int e = blockIdx.x * 256 + t;
    if (e >= E) return;
    int s = esrc[e], d = edst[e];

    float4 ps = g_pos4[s];
    float4 pd = g_pos4[d];
    float4 f  = g_feat4[s];

    float dx = pd.x - ps.x, dy = pd.y - ps.y, dz = pd.z - ps.z;
    float dist = sqrtf(dx * dx + dy * dy + dz * dz);

    float em[3];
#pragma unroll
    for (int i = 0; i < 3; i++) {
        float tt = (dist - 0.75f * (float)(i + 1)) * (1.0f / 0.75f);
        float q = 1.0f - tt * tt;
        em[i] = (q > 0.0f) ? EMBC * __expf(__fdividef(-2.0f, q)) : 0.0f;
    }
    g_emb4[e] = make_float4(em[0], em[1], em[2], 0.f);

    float rlo[8], rhi[8];
    compute_r_pairs(sW1u, em[0], em[1], em[2], rlo, rhi);

    u64 acc[6];
#pragma unroll
    for (int jp = 0; jp < 6; jp++) acc[jp] = 0ull;
#pragma unroll
    for (int kp = 0; kp < 8; kp++) {
        u64 ra = pack2(rlo[kp], rlo[kp]);
        u64 rb = pack2(rhi[kp], rhi[kp]);
        const u64x2* wa = (const u64x2*)&sW2u[(2 * kp) * 6];
        const u64x2* wb = (const u64x2*)&sW2u[(2 * kp + 1) * 6];
#pragma unroll
        for (int q = 0; q < 3; q++) {
            u64x2 w = wa[q];
            fma2(acc[2 * q], ra, w.x); fma2(acc[2 * q + 1], ra, w.y);
        }
#pragma unroll
        for (int q = 0; q < 3; q++) {
            u64x2 w = wb[q];
            fma2(acc[2 * q], rb, w.x); fma2(acc[2 * q + 1], rb, w.y);
        }
    }

    // msg pairs: m01 = sum_u f_u * acc[u*2], m23 = sum_u f_u * acc[u*2+1]
    u64 fu[3] = { pack2(f.x, f.x), pack2(f.y, f.y), pack2(f.z, f.z) };
    u64 m01 = 0ull, m23 = 0ull;
#pragma unroll
    for (int u = 0; u < 3; u++) { fma2(m01, fu[u], acc[u * 2]); fma2(m23, fu[u], acc[u * 2 + 1]); }
    float m0, m1, m2, m3;
    unpack2(m01, m0, m1); unpack2(m23, m2, m3);
    red_add_v4(&xout[d], m0, m1, m2, m3);
}

// ============================================================================
// core conv: r + 16x16 GEMM (vec LDS) + msg; also zeroes zbuf for next pass
__global__ void __launch_bounds__(256) core_kernel(
    const int* __restrict__ esrc, const int* __restrict__ edst,
    const float* __restrict__ w1, const float* __restrict__ w2, // w2 raw [16,48]
    const float4* __restrict__ xin, float4* __restrict__ xout,
    float4* __restrict__ zbuf, int zn, int E)
{
    __shared__ __align__(16) u64 sW1u[24];
    __shared__ __align__(16) u64 sW2u[128];  // [k*8 + jp], CCORE folded; rows 64B aligned
    int t = threadIdx.x;
    if (t < 24) {
        int i = t / 8, kp = t % 8;
        sW1u[t] = pack2(w1[i * 16 + 2 * kp], w1[i * 16 + 2 * kp + 1]);
    }
    if (t < 128) {
        int k = t >> 3, jp = t & 7;
        sW2u[t] = pack2(CCORE * w2[k * 48 + 2 * jp], CCORE * w2[k * 48 + 2 * jp + 1]);
    }
    __syncthreads();

    int gid = blockIdx.x * 256 + t;
    if (gid < zn) zbuf[gid] = make_float4(0.f, 0.f, 0.f, 0.f);

    int e = gid;
    if (e >= E) return;
    int s = esrc[e], d = edst[e];

    float4 x  = xin[s];
    float4 em = g_emb4[e];

    float rlo[8], rhi[8];
    compute_r_pairs(sW1u, em.x, em.y, em.z, rlo, rhi);

    u64 acc[8];
#pragma unroll
    for (int jp = 0; jp < 8; jp++) acc[jp] = 0ull;
#pragma unroll
    for (int kp = 0; kp < 8; kp++) {
        u64 ra = pack2(rlo[kp], rlo[kp]);
        u64 rb = pack2(rhi[kp], rhi[kp]);
        const u64x2* wa = (const u64x2*)&sW2u[(2 * kp) * 8];
        const u64x2* wb = (const u64x2*)&sW2u[(2 * kp + 1) * 8];
#pragma unroll
        for (int q = 0; q < 4; q++) {
            u64x2 w = wa[q];
            fma2(acc[2 * q], ra, w.x); fma2(acc[2 * q + 1], ra, w.y);
        }
#pragma unroll
        for (int q = 0; q < 4; q++) {
            u64x2 w = wb[q];
            fma2(acc[2 * q], rb, w.x); fma2(acc[2 * q + 1], rb, w.y);
        }
    }

    // msg pairs: jp = u*2 + wp; m01 over wp=0 (out 0,1), m23 over wp=1 (out 2,3)
    u64 xu[4] = { pack2(x.x, x.x), pack2(x.y, x.y), pack2(x.z, x.z), pack2(x.w, x.w) };
    u64 m01 = 0ull, m23 = 0ull;
#pragma unroll
    for (int u = 0; u < 4; u++) { fma2(m01, xu[u], acc[u * 2]); fma2(m23, xu[u], acc[u * 2 + 1]); }
    float m0, m1, m2, m3;
    unpack2(m01, m0, m1); unpack2(m23, m2, m3);
    red_add_v4(&xout[d], m0, m1, m2, m3);
}

// ============================================================================
// conv3 fused with Conv1d(16,2,1)
__global__ void __launch_bounds__(256) conv3_kernel(
    const int* __restrict__ esrc, const int* __restrict__ edst,
    const float* __restrict__ w1,
    const float4* __restrict__ xin, float* __restrict__ out, int E)
{
    __shared__ __align__(16) u64 sW1u[24];
    __shared__ __align__(16) u64 sMu[64];    // [k*4 + u] = (M[k,u,0], M[k,u,1]); rows 32B
    int t = threadIdx.x;
    if (t < 24) {
        int i = t / 8, kp = t % 8;
        sW1u[t] = pack2(w1[i * 16 + 2 * kp], w1[i * 16 + 2 * kp + 1]);
    }
    if (t < 64) {
        int k = t >> 2, u = t & 3;
        sMu[t] = pack2(g_M[k * 8 + u * 2], g_M[k * 8 + u * 2 + 1]);
    }
    __syncthreads();

    int e = blockIdx.x * 256 + t;
    if (e >= E) return;
    int s = esrc[e], d = edst[e];

    float4 x  = xin[s];
    float4 em = g_emb4[e];

    float rlo[8], rhi[8];
    compute_r_pairs(sW1u, em.x, em.y, em.z, rlo, rhi);

    u64 acc[4];
#pragma unroll
    for (int u = 0; u < 4; u++) acc[u] = 0ull;
#pragma unroll
    for (int kp = 0; kp < 8; kp++) {
        u64 ra = pack2(rlo[kp], rlo[kp]);
        u64 rb = pack2(rhi[kp], rhi[kp]);
        const u64x2* wa = (const u64x2*)&sMu[(2 * kp) * 4];
        const u64x2* wb = (const u64x2*)&sMu[(2 * kp + 1) * 4];
#pragma unroll
        for (int q = 0; q < 2; q++) {
            u64x2 w = wa[q];
            fma2(acc[2 * q], ra, w.x); fma2(acc[2 * q + 1], ra, w.y);
        }
#pragma unroll
        for (int q = 0; q < 2; q++) {
            u64x2 w = wb[q];
            fma2(acc[2 * q], rb, w.x); fma2(acc[2 * q + 1], rb, w.y);
        }
    }

    u64 xu[4] = { pack2(x.x, x.x), pack2(x.y, x.y), pack2(x.z, x.z), pack2(x.w, x.w) };
    u64 mc = 0ull;
#pragma unroll
    for (int u = 0; u < 4; u++) fma2(mc, xu[u], acc[u]);
    float m0, m1;
    unpack2(mc, m0, m1);
    red_add_v2(out + 2 * d, m0, m1);
}

// ============================================================================
extern "C" void kernel_launch(void* const* d_in, const int* in_sizes, int n_in,
                              void* d_out, int out_size)
{
    const float* pos     = (const float*)d_in[0];
    const float* feat    = (const float*)d_in[1];
    const int*   esrc    = (const int*)  d_in[2];
    const int*   edst    = (const int*)  d_in[3];
    const float* fc1_w1  = (const float*)d_in[4];
    const float* fc1_w2  = (const float*)d_in[5];
    const float* core_w1 = (const float*)d_in[6];   // [3,3,16]
    const float* core_w2 = (const float*)d_in[7];   // [3,16,48]
    const float* fc3_w1  = (const float*)d_in[8];
    const float* fc3_w2  = (const float*)d_in[9];
    const float* conv_w  = (const float*)d_in[10];
    const float* conv_b  = (const float*)d_in[11];
    float* out = (float*)d_out;

    int E = in_sizes[2];
    int n = in_sizes[0] / 3;

    float4 *xA, *xB, *xC;
    cudaGetSymbolAddress((void**)&xA, g_xA);
    cudaGetSymbolAddress((void**)&xB, g_xB);
    cudaGetSymbolAddress((void**)&xC, g_xC);

    int eb = (E + 255) / 256;
    int nb = (n + 255) / 256;

    mprep_kernel<<<1, 128>>>(fc3_w2, conv_w);
    prep_kernel<<<nb, 256>>>(pos, feat, conv_b, out, n);

    conv1_kernel<<<eb, 256>>>(esrc, edst, fc1_w1, fc1_w2, xA, E);
    // core1: A->B, zero C for core2's output
    core_kernel<<<eb, 256>>>(esrc, edst, core_w1 + 0,  core_w2 + 0,    xA, xB, xC, n, E);
    // core2: B->C, zero A for core3's output
    core_kernel<<<eb, 256>>>(esrc, edst, core_w1 + 48, core_w2 + 768,  xB, xC, xA, n, E);
    // core3: C->A
    core_kernel<<<eb, 256>>>(esrc, edst, core_w1 + 96, core_w2 + 1536, xC, xA, (float4*)0, 0, E);

    conv3_kernel<<<eb, 256>>>(esrc, edst, fc3_w1, xA, out, E);
}